// round 3
// baseline (speedup 1.0000x reference)
#include <cuda_runtime.h>

// LIF recurrence: input [B=32, T=8, C=128, H=32, W=32] fp32, output spikes same shape.
// mem = 0.5*mem + x_t; s = (mem - 1.0 > 0); mem *= (1 - s).
//
// R3: reads use __ldcs (evict-first streaming) so the never-reused input
// stream doesn't displace dirty output lines in L2; stores keep default
// policy so the write stream is absorbed by the 126MB L2 as long as possible.
// Loads remain front-batched (MLP=8/thread).

#define TAU  0.5f
#define V_TH 1.0f

#define CHW4  32768   // (128*32*32)/4
#define CHW4_SHIFT 15
#define CHW4_MASK  32767
#define T_STEPS 8

__global__ void __launch_bounds__(512)
lif_kernel(const float4* __restrict__ x, float4* __restrict__ out)
{
    int idx = blockIdx.x * blockDim.x + threadIdx.x;
    int b = idx >> CHW4_SHIFT;        // batch
    int s = idx & CHW4_MASK;          // spatial float4 index within CHW

    long base = ((long)b * T_STEPS) * CHW4 + s;
    const float4* xp = x + base;
    float4* op = out + base;

    // Front-batched streaming loads: 8 independent LDG.128 (evict-first).
    float4 v[T_STEPS];
    #pragma unroll
    for (int t = 0; t < T_STEPS; t++) {
        v[t] = __ldcs(xp + t * CHW4);
    }

    float m0 = 0.f, m1 = 0.f, m2 = 0.f, m3 = 0.f;

    #pragma unroll
    for (int t = 0; t < T_STEPS; t++) {
        m0 = fmaf(TAU, m0, v[t].x);
        m1 = fmaf(TAU, m1, v[t].y);
        m2 = fmaf(TAU, m2, v[t].z);
        m3 = fmaf(TAU, m3, v[t].w);

        float s0 = (m0 - V_TH > 0.f) ? 1.f : 0.f;
        float s1 = (m1 - V_TH > 0.f) ? 1.f : 0.f;
        float s2 = (m2 - V_TH > 0.f) ? 1.f : 0.f;
        float s3 = (m3 - V_TH > 0.f) ? 1.f : 0.f;

        op[t * CHW4] = make_float4(s0, s1, s2, s3);

        m0 = (s0 > 0.f) ? 0.f : m0;
        m1 = (s1 > 0.f) ? 0.f : m1;
        m2 = (s2 > 0.f) ? 0.f : m2;
        m3 = (s3 > 0.f) ? 0.f : m3;
    }
}

extern "C" void kernel_launch(void* const* d_in, const int* in_sizes, int n_in,
                              void* d_out, int out_size)
{
    const float* x = (const float*)d_in[0];
    float* out = (float*)d_out;

    const int total = 32 * CHW4;            // B * CHW/4 = 1,048,576 threads
    const int threads = 512;
    const int blocks = total / threads;     // 2048

    lif_kernel<<<blocks, threads>>>((const float4*)x, (float4*)out);
}